// round 3
// baseline (speedup 1.0000x reference)
#include <cuda_runtime.h>
#include <cstdint>
#include <math.h>

#define BB 32
#define TT 2048
#define FF 64
#define HH 256
#define GG 768
#define MTOT (BB*TT)

// scratch (static device arrays: the sanctioned no-alloc workaround)
__device__ float g_xn[(size_t)MTOT*FF];
__device__ float g_xb[(size_t)MTOT*GG];
__device__ float g_h1[(size_t)MTOT*HH];
__device__ float g_h2[BB*HH];

// ---------------- LayerNorm: one warp per 64-feature row ----------------
__global__ void __launch_bounds__(256) ln_kernel(const float* __restrict__ x,
        const float* __restrict__ gamma, const float* __restrict__ beta,
        float* __restrict__ xn)
{
    int row  = blockIdx.x * 8 + (threadIdx.x >> 5);
    int lane = threadIdx.x & 31;
    const float* xr = x + (size_t)row * FF;
    float v0 = xr[lane], v1 = xr[lane + 32];
    float s = v0 + v1;
    #pragma unroll
    for (int o = 16; o > 0; o >>= 1) s += __shfl_xor_sync(0xffffffffu, s, o);
    float mu = s * (1.f / FF);
    float d0 = v0 - mu, d1 = v1 - mu;
    float q = d0 * d0 + d1 * d1;
    #pragma unroll
    for (int o = 16; o > 0; o >>= 1) q += __shfl_xor_sync(0xffffffffu, q, o);
    float inv = rsqrtf(q * (1.f / FF) + 1e-3f);
    float* orow = xn + (size_t)row * FF;
    orow[lane]      = d0 * inv * gamma[lane]      + beta[lane];
    orow[lane + 32] = d1 * inv * gamma[lane + 32] + beta[lane + 32];
}

// ------------- GEMM + bias: C[M,N]=A@B+bias, BM=BN=64, BK=16 -------------
__global__ void __launch_bounds__(256) gemm_bias(const float* __restrict__ A,
        const float* __restrict__ B, const float* __restrict__ bias,
        float* __restrict__ C, int M, int N, int K)
{
    __shared__ __align__(16) float As[16][68];
    __shared__ __align__(16) float Bs[16][64];
    const int tid = threadIdx.x;
    const int bn = blockIdx.x * 64, bm = blockIdx.y * 64;
    const int arow = tid >> 2,  ak = (tid & 3)  << 2;
    const int brow = tid >> 4,  bc = (tid & 15) << 2;
    const int rm   = (tid >> 4) << 2, rn = (tid & 15) << 2;
    float c[4][4] = {};
    for (int k0 = 0; k0 < K; k0 += 16) {
        float4 a4 = *(const float4*)(A + (size_t)(bm + arow) * K + k0 + ak);
        As[ak + 0][arow] = a4.x; As[ak + 1][arow] = a4.y;
        As[ak + 2][arow] = a4.z; As[ak + 3][arow] = a4.w;
        *(float4*)&Bs[brow][bc] = *(const float4*)(B + (size_t)(k0 + brow) * N + bn + bc);
        __syncthreads();
        #pragma unroll
        for (int k = 0; k < 16; ++k) {
            float4 av = *(const float4*)&As[k][rm];
            float4 bv = *(const float4*)&Bs[k][rn];
            c[0][0] += av.x*bv.x; c[0][1] += av.x*bv.y; c[0][2] += av.x*bv.z; c[0][3] += av.x*bv.w;
            c[1][0] += av.y*bv.x; c[1][1] += av.y*bv.y; c[1][2] += av.y*bv.z; c[1][3] += av.y*bv.w;
            c[2][0] += av.z*bv.x; c[2][1] += av.z*bv.y; c[2][2] += av.z*bv.z; c[2][3] += av.z*bv.w;
            c[3][0] += av.w*bv.x; c[3][1] += av.w*bv.y; c[3][2] += av.w*bv.z; c[3][3] += av.w*bv.w;
        }
        __syncthreads();
    }
    float4 bv = *(const float4*)(bias + bn + rn);
    #pragma unroll
    for (int i = 0; i < 4; ++i) {
        float4 o;
        o.x = c[i][0] + bv.x; o.y = c[i][1] + bv.y;
        o.z = c[i][2] + bv.z; o.w = c[i][3] + bv.w;
        *(float4*)(C + (size_t)(bm + rm + i) * N + bn + rn) = o;
    }
}

// --------- Persistent GRU: 32 clusters x 4 CTAs, 1 cluster/batch ---------
// CTA rank owns h-cols [64r,64r+64) -> gate cols {j, 256+j, 512+j}.
// rk slice 256x192 fp32 in SMEM; h double-buffered; DSMEM push + 1 cluster
// barrier per step.
#define GRU_SMEM_FLOATS (49152 + 512 + 1536 + 192 + 192)
__global__ void __launch_bounds__(256, 1) __cluster_dims__(4, 1, 1)
gru_kernel(const float* __restrict__ xb, const float* __restrict__ rk,
           const float* __restrict__ brec, float* __restrict__ seqout,
           float* __restrict__ hfinal, int write_seq)
{
    extern __shared__ float sm[];
    float* wsm  = sm;              // [k=256][g=3][j=64]
    float* hsm  = wsm + 49152;     // 2 x 256
    float* red  = hsm + 512;       // [8 warps][16 colgrp][12]
    float* gate = red + 1536;      // [3][64]
    float* brs  = gate + 192;      // [3][64]

    const int tid   = threadIdx.x;
    const int rank  = blockIdx.x & 3;
    const int batch = blockIdx.x >> 2;
    const int jbase = rank * 64;

    for (int e = tid; e < 49152; e += 256) {
        int j = e & 63, g = (e >> 6) % 3, k = e / 192;
        wsm[e] = rk[(size_t)k * GG + g * 256 + jbase + j];
    }
    if (tid < 192) brs[tid] = brec[(tid >> 6) * 256 + jbase + (tid & 63)];
    hsm[tid] = 0.f; hsm[256 + tid] = 0.f;

    // precompute remote peer addresses for both h buffers
    uint32_t rem[2][3];
    if (tid < 64) {
        #pragma unroll
        for (int b = 0; b < 2; ++b) {
            uint32_t la = (uint32_t)__cvta_generic_to_shared(hsm + b * 256 + jbase + tid);
            #pragma unroll
            for (int p = 0; p < 3; ++p) {
                uint32_t tr = (uint32_t)((rank + 1 + p) & 3);
                asm("mapa.shared::cluster.u32 %0, %1, %2;"
                    : "=r"(rem[b][p]) : "r"(la), "r"(tr));
            }
        }
    }
    __syncthreads();
    asm volatile("barrier.cluster.arrive.aligned;\n\tbarrier.cluster.wait.aligned;" ::: "memory");

    const int c4    = (tid & 15) * 4;
    const int kbase = (tid >> 4) * 16;
    const int warp  = tid >> 5;
    const bool lo   = (tid & 31) < 16;
    const float* xrow = xb + (size_t)batch * TT * GG;
    float* srow = seqout + (size_t)batch * TT * HH;

    for (int t = 0; t < TT; ++t) {
        const float* cur = hsm + ((t & 1) << 8);
        float*       nxt = hsm + (((t & 1) ^ 1) << 8);
        const int    nb  = (t & 1) ^ 1;

        float xz = 0.f, xr_ = 0.f, xh = 0.f;
        if (tid < 64) {
            const float* xp = xrow + (size_t)t * GG + jbase + tid;
            xz = __ldg(xp); xr_ = __ldg(xp + 256); xh = __ldg(xp + 512);
        }

        float a[12];
        #pragma unroll
        for (int v = 0; v < 12; ++v) a[v] = 0.f;
        #pragma unroll
        for (int kk = 0; kk < 16; kk += 4) {
            float4 h4 = *(const float4*)(cur + kbase + kk);
            float hv4[4] = {h4.x, h4.y, h4.z, h4.w};
            #pragma unroll
            for (int u = 0; u < 4; ++u) {
                const float* w = wsm + (kbase + kk + u) * 192 + c4;
                float hv = hv4[u];
                float4 wz = *(const float4*)(w);
                float4 wr = *(const float4*)(w + 64);
                float4 wh = *(const float4*)(w + 128);
                a[0]+=hv*wz.x; a[1]+=hv*wz.y; a[2] +=hv*wz.z; a[3] +=hv*wz.w;
                a[4]+=hv*wr.x; a[5]+=hv*wr.y; a[6] +=hv*wr.z; a[7] +=hv*wr.w;
                a[8]+=hv*wh.x; a[9]+=hv*wh.y; a[10]+=hv*wh.z; a[11]+=hv*wh.w;
            }
        }
        #pragma unroll
        for (int v = 0; v < 12; ++v) a[v] += __shfl_xor_sync(0xffffffffu, a[v], 16);
        if (lo) {
            float* r = red + (warp * 16 + (tid & 15)) * 12;
            #pragma unroll
            for (int v = 0; v < 12; ++v) r[v] = a[v];
        }
        __syncthreads();
        if (tid < 192) {
            int cc = tid / 12, v = tid - cc * 12;
            float s = 0.f;
            #pragma unroll
            for (int w8 = 0; w8 < 8; ++w8) s += red[(w8 * 16 + cc) * 12 + v];
            gate[(v >> 2) * 64 + cc * 4 + (v & 3)] = s;
        }
        __syncthreads();
        if (tid < 64) {
            float gz = gate[tid]       + brs[tid]       + xz;
            float gr = gate[64 + tid]  + brs[64 + tid]  + xr_;
            float gh = gate[128 + tid] + brs[128 + tid];
            float z  = 1.f / (1.f + expf(-gz));
            float r  = 1.f / (1.f + expf(-gr));
            float hh = tanhf(xh + r * gh);
            float hp = cur[jbase + tid];
            float hn = z * hp + (1.f - z) * hh;
            nxt[jbase + tid] = hn;
            #pragma unroll
            for (int p = 0; p < 3; ++p)
                asm volatile("st.shared::cluster.f32 [%0], %1;"
                             :: "r"(rem[nb][p]), "f"(hn) : "memory");
            if (write_seq) srow[(size_t)t * HH + jbase + tid] = hn;
        }
        asm volatile("barrier.cluster.arrive.aligned;\n\tbarrier.cluster.wait.aligned;" ::: "memory");
    }
    if (!write_seq && rank == 0) hfinal[batch * HH + tid] = hsm[(TT & 1) * 256 + tid];
}

// ---------------- Dense: out[32,64] = h2 @ wd + bd ----------------
__global__ void __launch_bounds__(256) dense_kernel(const float* __restrict__ h2,
        const float* __restrict__ wd, const float* __restrict__ bd,
        float* __restrict__ out)
{
    int o = blockIdx.x * 256 + threadIdx.x;
    int b = o >> 6, j = o & 63;
    float s = bd[j];
    for (int k = 0; k < HH; ++k) s += h2[b * HH + k] * wd[k * 64 + j];
    out[o] = s;
}

extern "C" void kernel_launch(void* const* d_in, const int* in_sizes, int n_in,
                              void* d_out, int out_size) {
    const float* x     = (const float*)d_in[0];
    const float* gamma = (const float*)d_in[1];
    const float* beta  = (const float*)d_in[2];
    const float* k1    = (const float*)d_in[3];
    const float* rk1   = (const float*)d_in[4];
    const float* b1    = (const float*)d_in[5];
    const float* k2    = (const float*)d_in[6];
    const float* rk2   = (const float*)d_in[7];
    const float* b2    = (const float*)d_in[8];
    const float* wd    = (const float*)d_in[9];
    const float* bd    = (const float*)d_in[10];
    float* out = (float*)d_out;

    float *xn, *xbuf, *h1, *h2;
    cudaGetSymbolAddress((void**)&xn,   g_xn);
    cudaGetSymbolAddress((void**)&xbuf, g_xb);
    cudaGetSymbolAddress((void**)&h1,   g_h1);
    cudaGetSymbolAddress((void**)&h2,   g_h2);

    cudaFuncSetAttribute(gru_kernel, cudaFuncAttributeMaxDynamicSharedMemorySize,
                         GRU_SMEM_FLOATS * 4);

    ln_kernel<<<MTOT / 8, 256>>>(x, gamma, beta, xn);
    gemm_bias<<<dim3(GG / 64, MTOT / 64), 256>>>(xn, k1, b1, xbuf, MTOT, GG, FF);
    gru_kernel<<<128, 256, GRU_SMEM_FLOATS * 4>>>(xbuf, rk1, b1 + GG, h1, h2, 1);
    gemm_bias<<<dim3(GG / 64, MTOT / 64), 256>>>(h1, k2, b2, xbuf, MTOT, GG, HH);
    gru_kernel<<<128, 256, GRU_SMEM_FLOATS * 4>>>(xbuf, rk2, b2 + GG, h1, h2, 0);
    dense_kernel<<<(BB * 64) / 256, 256>>>(h2, wd, bd, out);
}